// round 4
// baseline (speedup 1.0000x reference)
#include <cuda_runtime.h>

#define BB 2
#define LL 2048
#define DD 1024
#define NS 16
#define RR 64
#define EE 96
#define NC 32
#define LC 64   /* LL / NC */

typedef unsigned long long u64;

// ---------------- packed f32x2 helpers ----------------
__device__ __forceinline__ u64 pk2(float x, float y) {
    u64 r; asm("mov.b64 %0,{%1,%2};" : "=l"(r) : "f"(x), "f"(y)); return r;
}
__device__ __forceinline__ float2 upk(u64 v) {
    float2 f; asm("mov.b64 {%0,%1},%2;" : "=f"(f.x), "=f"(f.y) : "l"(v)); return f;
}
__device__ __forceinline__ u64 fma2_(u64 a, u64 b, u64 c) {
    u64 d; asm("fma.rn.f32x2 %0,%1,%2,%3;" : "=l"(d) : "l"(a), "l"(b), "l"(c)); return d;
}
__device__ __forceinline__ u64 mul2_(u64 a, u64 b) {
    u64 d; asm("mul.rn.f32x2 %0,%1,%2;" : "=l"(d) : "l"(a), "l"(b)); return d;
}

// ---------------- scratch ----------------
__device__ float  g_part[8 * BB*LL * EE];    // GEMM1 split-K partials
__device__ float  g_xdbl[BB*LL*EE];          // (b,l,96): [0:64)=dt_in, [64:80)=B, [80:96)=C
__device__ float  g_dt[BB*LL*DD];            // softplus(dt_proj) (fallback path)
__device__ float2 g_ed[BB*LL*DD];            // (e1 = exp(dt*a0), dtx = dt*x)
__device__ u64    g_P  [NC*BB*DD*8];         // per-chunk cumulative dA product
__device__ u64    g_S  [NC*BB*DD*8];         // per-chunk local final state
__device__ u64    g_hin[NC*BB*DD*8];         // corrected chunk-entry state

// =========================================================================
// GEMM1 (split-K partials)
// =========================================================================
#define G1_BM 64
#define G1_BN 96
#define G1_BK 32
#define G1_KC 128

__global__ void __launch_bounds__(96) gemm1_partial(
    const float* __restrict__ X, const float* __restrict__ Wx)
{
    __shared__ float As[G1_BK][G1_BM + 4];
    __shared__ float Bs[G1_BK][G1_BN + 4];
    const int t  = threadIdx.x;
    const int tx = t % 12;
    const int ty = t / 12;
    const int m0 = blockIdx.x * G1_BM;
    const int ks = blockIdx.y;

    u64 acc[8][4];
    #pragma unroll
    for (int i = 0; i < 8; i++)
        #pragma unroll
        for (int j = 0; j < 4; j++) acc[i][j] = 0ull;

    for (int kt = 0; kt < G1_KC / G1_BK; kt++) {
        const int k0 = ks * G1_KC + kt * G1_BK;
        for (int i = t; i < 512; i += 96) {
            int row = i >> 3, q = i & 7;
            float4 v = *(const float4*)&X[(m0 + row) * DD + k0 + q * 4];
            As[q*4+0][row] = v.x; As[q*4+1][row] = v.y;
            As[q*4+2][row] = v.z; As[q*4+3][row] = v.w;
        }
        for (int i = t; i < 768; i += 96) {
            int n = i >> 3, q = i & 7;
            float4 v = *(const float4*)&Wx[n * DD + k0 + q * 4];
            Bs[q*4+0][n] = v.x; Bs[q*4+1][n] = v.y;
            Bs[q*4+2][n] = v.z; Bs[q*4+3][n] = v.w;
        }
        __syncthreads();
        #pragma unroll
        for (int kk = 0; kk < G1_BK; kk++) {
            float4 av0 = *(const float4*)&As[kk][ty * 8];
            float4 av1 = *(const float4*)&As[kk][ty * 8 + 4];
            ulonglong2 bq0 = *(const ulonglong2*)&Bs[kk][tx * 8];
            ulonglong2 bq1 = *(const ulonglong2*)&Bs[kk][tx * 8 + 4];
            u64 b2[4] = {bq0.x, bq0.y, bq1.x, bq1.y};
            float a[8] = {av0.x, av0.y, av0.z, av0.w, av1.x, av1.y, av1.z, av1.w};
            #pragma unroll
            for (int i = 0; i < 8; i++) {
                u64 a2 = pk2(a[i], a[i]);
                #pragma unroll
                for (int j = 0; j < 4; j++)
                    acc[i][j] = fma2_(a2, b2[j], acc[i][j]);
            }
        }
        __syncthreads();
    }

    float* outp = g_part + (size_t)ks * (BB*LL*EE);
    #pragma unroll
    for (int i = 0; i < 8; i++) {
        int m = m0 + ty * 8 + i;
        float2 p0 = upk(acc[i][0]), p1 = upk(acc[i][1]);
        float2 p2 = upk(acc[i][2]), p3 = upk(acc[i][3]);
        *(float4*)&outp[m * EE + tx * 8]     = make_float4(p0.x, p0.y, p1.x, p1.y);
        *(float4*)&outp[m * EE + tx * 8 + 4] = make_float4(p2.x, p2.y, p3.x, p3.y);
    }
}

__global__ void __launch_bounds__(256) gemm1_reduce()
{
    const int i = blockIdx.x * 256 + threadIdx.x;      // < 98304
    const float4* p = (const float4*)g_part;
    float4 s = p[i];
    #pragma unroll
    for (int ks = 1; ks < 8; ks++) {
        float4 v = p[ks * 98304 + i];
        s.x += v.x; s.y += v.y; s.z += v.z; s.w += v.w;
    }
    ((float4*)g_xdbl)[i] = s;
}

// =========================================================================
// GEMM2 + softplus + ed precompute:
//   dt = softplus(xdbl[:, :64] @ Wdt^T + bdt)
//   g_dt = dt;  g_ed = (exp(dt*a0_d), dt * x)
// =========================================================================
__global__ void __launch_bounds__(128) gemm2_softplus(
    const float* __restrict__ Wdt, const float* __restrict__ bdt,
    const float* __restrict__ X, const float* __restrict__ A_log)
{
    __shared__ float As[32][64 + 4];
    __shared__ float Bs[32][128 + 4];
    const int t  = threadIdx.x;
    const int tx = t % 16;
    const int ty = t / 16;
    const int m0 = blockIdx.x * 64;
    const int n0 = blockIdx.y * 128;

    u64 acc[8][4];
    #pragma unroll
    for (int i = 0; i < 8; i++)
        #pragma unroll
        for (int j = 0; j < 4; j++) acc[i][j] = 0ull;

    for (int kt = 0; kt < 2; kt++) {
        const int k0 = kt * 32;
        for (int i = t; i < 512; i += 128) {
            int row = i >> 3, q = i & 7;
            float4 v = *(const float4*)&g_xdbl[(m0 + row) * EE + k0 + q * 4];
            As[q*4+0][row] = v.x; As[q*4+1][row] = v.y;
            As[q*4+2][row] = v.z; As[q*4+3][row] = v.w;
        }
        for (int i = t; i < 1024; i += 128) {
            int n = i >> 3, q = i & 7;
            float4 v = *(const float4*)&Wdt[(n0 + n) * RR + k0 + q * 4];
            Bs[q*4+0][n] = v.x; Bs[q*4+1][n] = v.y;
            Bs[q*4+2][n] = v.z; Bs[q*4+3][n] = v.w;
        }
        __syncthreads();
        #pragma unroll
        for (int kk = 0; kk < 32; kk++) {
            float4 av0 = *(const float4*)&As[kk][ty * 8];
            float4 av1 = *(const float4*)&As[kk][ty * 8 + 4];
            ulonglong2 bq0 = *(const ulonglong2*)&Bs[kk][tx * 8];
            ulonglong2 bq1 = *(const ulonglong2*)&Bs[kk][tx * 8 + 4];
            u64 b2[4] = {bq0.x, bq0.y, bq1.x, bq1.y};
            float a[8] = {av0.x, av0.y, av0.z, av0.w, av1.x, av1.y, av1.z, av1.w};
            #pragma unroll
            for (int i = 0; i < 8; i++) {
                u64 a2 = pk2(a[i], a[i]);
                #pragma unroll
                for (int j = 0; j < 4; j++)
                    acc[i][j] = fma2_(a2, b2[j], acc[i][j]);
            }
        }
        __syncthreads();
    }

    float4 bi0 = *(const float4*)&bdt[n0 + tx * 8];
    float4 bi1 = *(const float4*)&bdt[n0 + tx * 8 + 4];
    float bi[8] = {bi0.x, bi0.y, bi0.z, bi0.w, bi1.x, bi1.y, bi1.z, bi1.w};
    float a0[8];
    #pragma unroll
    for (int j = 0; j < 8; j++)
        a0[j] = -__expf(A_log[(n0 + tx * 8 + j) * NS]);

    #pragma unroll
    for (int i = 0; i < 8; i++) {
        int m = m0 + ty * 8 + i;
        float2 p[4] = {upk(acc[i][0]), upk(acc[i][1]), upk(acc[i][2]), upk(acc[i][3])};
        float v[8] = {p[0].x, p[0].y, p[1].x, p[1].y, p[2].x, p[2].y, p[3].x, p[3].y};
        float4 xv0 = *(const float4*)&X[m * DD + n0 + tx * 8];
        float4 xv1 = *(const float4*)&X[m * DD + n0 + tx * 8 + 4];
        float xv[8] = {xv0.x, xv0.y, xv0.z, xv0.w, xv1.x, xv1.y, xv1.z, xv1.w};
        float e1[8], dtx[8];
        #pragma unroll
        for (int j = 0; j < 8; j++) {
            float w = v[j] + bi[j];
            float dt = (w > 20.f) ? w : log1pf(__expf(w));
            v[j] = dt;
            e1[j]  = __expf(dt * a0[j]);
            dtx[j] = dt * xv[j];
        }
        *(float4*)&g_dt[m * DD + n0 + tx * 8]     = make_float4(v[0], v[1], v[2], v[3]);
        *(float4*)&g_dt[m * DD + n0 + tx * 8 + 4] = make_float4(v[4], v[5], v[6], v[7]);
        float4* edp = (float4*)&g_ed[m * DD + n0 + tx * 8];
        edp[0] = make_float4(e1[0], dtx[0], e1[1], dtx[1]);
        edp[1] = make_float4(e1[2], dtx[2], e1[3], dtx[3]);
        edp[2] = make_float4(e1[4], dtx[4], e1[5], dtx[5]);
        edp[3] = make_float4(e1[6], dtx[6], e1[7], dtx[7]);
    }
}

// ---------------- packed power ladder: dA2[k] = (e1^(2k+1), e1^(2k+2)) ----------------
__device__ __forceinline__ void pow_ladder2(float e1, u64* dA2) {
    float e2 = e1*e1, e4 = e2*e2, e8 = e4*e4;
    u64 d01 = pk2(e1, e2);
    u64 s2 = pk2(e2, e2), s4 = pk2(e4, e4), s8 = pk2(e8, e8);
    dA2[0] = d01;
    dA2[1] = mul2_(d01, s2);
    dA2[2] = mul2_(d01, s4);
    dA2[3] = mul2_(dA2[1], s4);
    dA2[4] = mul2_(d01, s8);
    dA2[5] = mul2_(dA2[1], s8);
    dA2[6] = mul2_(dA2[2], s8);
    dA2[7] = mul2_(dA2[3], s8);
}

// ---------------- pass 1: per-chunk local scan, emit (P, S) ----------------
__global__ void __launch_bounds__(128, 6) scan_pass1(
    const float* __restrict__ x, const float* __restrict__ A_log)
{
    __shared__ alignas(16) float Bsh[LC*NS];
    const int tid = threadIdx.x;
    const int d = blockIdx.x*128 + tid;
    const int b = blockIdx.y;
    const int c = blockIdx.z;
    const int l0 = c*LC;

    for (int i = tid; i < LC*NS; i += 128) {
        int l = i >> 4, n = i & 15;
        Bsh[i] = g_xdbl[(b*LL + l0 + l)*EE + RR + n];
    }
    __syncthreads();

    float an[NS];
    #pragma unroll
    for (int n=0;n<NS;n++) an[n] = -__expf(A_log[d*NS+n]);
    const float a0 = an[0];
    bool chain = true;
    #pragma unroll
    for (int n=1;n<NS;n++)
        chain = chain && (fabsf(an[n] - (float)(n+1)*a0) <= 2e-5f*(float)(n+1));

    const int base8 = ((c*BB + b)*DD + d)*8;

    if (chain) {
        const float2* edp = g_ed + (size_t)(b*LL + l0)*DD + d;
        u64 h2[8];
        #pragma unroll
        for (int k=0;k<8;k++) h2[k] = 0ull;
        float E = 1.f;
        #pragma unroll 16
        for (int l = 0; l < LC; l++) {
            float2 ed = edp[l*DD];
            float e1 = ed.x;
            u64 dtx2 = pk2(ed.y, ed.y);
            E *= e1;
            u64 dA2[8];
            pow_ladder2(e1, dA2);
            const ulonglong2* Bp = (const ulonglong2*)(Bsh + l*NS);
            ulonglong2 b0 = Bp[0], b1 = Bp[1], b2v = Bp[2], b3 = Bp[3];
            h2[0] = fma2_(dA2[0], h2[0], mul2_(dtx2, b0.x));
            h2[1] = fma2_(dA2[1], h2[1], mul2_(dtx2, b0.y));
            h2[2] = fma2_(dA2[2], h2[2], mul2_(dtx2, b1.x));
            h2[3] = fma2_(dA2[3], h2[3], mul2_(dtx2, b1.y));
            h2[4] = fma2_(dA2[4], h2[4], mul2_(dtx2, b2v.x));
            h2[5] = fma2_(dA2[5], h2[5], mul2_(dtx2, b2v.y));
            h2[6] = fma2_(dA2[6], h2[6], mul2_(dtx2, b3.x));
            h2[7] = fma2_(dA2[7], h2[7], mul2_(dtx2, b3.y));
        }
        u64 P2[8];
        pow_ladder2(E, P2);
        #pragma unroll
        for (int k=0;k<8;k++) { g_P[base8+k] = P2[k]; g_S[base8+k] = h2[k]; }
    } else {
        const float* dtp = g_dt + (size_t)(b*LL + l0)*DD + d;
        const float* xp  = x    + (size_t)(b*LL + l0)*DD + d;
        float h[NS], P[NS];
        #pragma unroll
        for (int n=0;n<NS;n++) { h[n]=0.f; P[n]=1.f; }
        for (int l = 0; l < LC; l++) {
            float dtv = dtp[l*DD];
            float dtx = dtv * xp[l*DD];
            #pragma unroll
            for (int n=0;n<NS;n++) {
                float dA = __expf(dtv * an[n]);
                P[n] *= dA;
                h[n] = fmaf(dA, h[n], dtx*Bsh[l*NS+n]);
            }
        }
        #pragma unroll
        for (int k=0;k<8;k++) { g_P[base8+k] = pk2(P[2*k],P[2*k+1]); g_S[base8+k] = pk2(h[2*k],h[2*k+1]); }
    }
}

// ---------------- pass 2: sequential chunk combine ----------------
__global__ void __launch_bounds__(256) scan_pass2()
{
    const int i = blockIdx.x*256 + threadIdx.x;     // over BB*DD*NS = 32768
    const float* Pf = (const float*)g_P;
    const float* Sf = (const float*)g_S;
    float* Hf = (float*)g_hin;
    float h = 0.f;
    #pragma unroll
    for (int c = 0; c < NC; c++) {
        int idx = c*(BB*DD*NS) + i;
        Hf[idx] = h;
        h = fmaf(Pf[idx], h, Sf[idx]);
    }
}

// ---------------- pass 3: final scan with corrected h0, emit y ----------------
__global__ void __launch_bounds__(128, 6) scan_pass3(
    const float* __restrict__ x, const float* __restrict__ A_log,
    const float* __restrict__ Dparam, float* __restrict__ out)
{
    __shared__ alignas(16) float Bsh[LC*NS];
    __shared__ alignas(16) float Csh[LC*NS];
    const int tid = threadIdx.x;
    const int d = blockIdx.x*128 + tid;
    const int b = blockIdx.y;
    const int c = blockIdx.z;
    const int l0 = c*LC;

    for (int i = tid; i < LC*NS; i += 128) {
        int l = i >> 4, n = i & 15;
        int base = (b*LL + l0 + l)*EE + RR;
        Bsh[i] = g_xdbl[base + n];
        Csh[i] = g_xdbl[base + NS + n];
    }
    __syncthreads();

    float an[NS];
    #pragma unroll
    for (int n=0;n<NS;n++) an[n] = -__expf(A_log[d*NS+n]);
    const float a0 = an[0];
    bool chain = true;
    #pragma unroll
    for (int n=1;n<NS;n++)
        chain = chain && (fabsf(an[n] - (float)(n+1)*a0) <= 2e-5f*(float)(n+1));

    const int base8 = ((c*BB + b)*DD + d)*8;
    const float Dp = Dparam[d];
    const float* xp  = x   + (size_t)(b*LL + l0)*DD + d;
    float* yp        = out + (size_t)(b*LL + l0)*DD + d;

    if (chain) {
        const float2* edp = g_ed + (size_t)(b*LL + l0)*DD + d;
        u64 h2[8];
        #pragma unroll
        for (int k=0;k<8;k++) h2[k] = g_hin[base8+k];
        #pragma unroll 8
        for (int l = 0; l < LC; l++) {
            float2 ed = edp[l*DD];
            float xv = xp[l*DD];
            float e1 = ed.x;
            u64 dtx2 = pk2(ed.y, ed.y);
            u64 dA2[8];
            pow_ladder2(e1, dA2);
            const ulonglong2* Bp = (const ulonglong2*)(Bsh + l*NS);
            const ulonglong2* Cp = (const ulonglong2*)(Csh + l*NS);
            ulonglong2 b0 = Bp[0], b1 = Bp[1], b2v = Bp[2], b3 = Bp[3];
            ulonglong2 c0 = Cp[0], c1 = Cp[1], c2v = Cp[2], c3 = Cp[3];
            u64 y2a = 0ull, y2b = 0ull;
            h2[0] = fma2_(dA2[0], h2[0], mul2_(dtx2, b0.x)); y2a = fma2_(h2[0], c0.x, y2a);
            h2[1] = fma2_(dA2[1], h2[1], mul2_(dtx2, b0.y)); y2b = fma2_(h2[1], c0.y, y2b);
            h2[2] = fma2_(dA2[2], h2[2], mul2_(dtx2, b1.x)); y2a = fma2_(h2[2], c1.x, y2a);
            h2[3] = fma2_(dA2[3], h2[3], mul2_(dtx2, b1.y)); y2b = fma2_(h2[3], c1.y, y2b);
            h2[4] = fma2_(dA2[4], h2[4], mul2_(dtx2, b2v.x)); y2a = fma2_(h2[4], c2v.x, y2a);
            h2[5] = fma2_(dA2[5], h2[5], mul2_(dtx2, b2v.y)); y2b = fma2_(h2[5], c2v.y, y2b);
            h2[6] = fma2_(dA2[6], h2[6], mul2_(dtx2, b3.x)); y2a = fma2_(h2[6], c3.x, y2a);
            h2[7] = fma2_(dA2[7], h2[7], mul2_(dtx2, b3.y)); y2b = fma2_(h2[7], c3.y, y2b);
            float2 ya = upk(y2a), yb = upk(y2b);
            yp[l*DD] = fmaf(xv, Dp, (ya.x+ya.y)+(yb.x+yb.y));
        }
    } else {
        const float* dtp = g_dt + (size_t)(b*LL + l0)*DD + d;
        float h[NS];
        #pragma unroll
        for (int k=0;k<8;k++) { float2 v = upk(g_hin[base8+k]); h[2*k]=v.x; h[2*k+1]=v.y; }
        for (int l = 0; l < LC; l++) {
            float dtv = dtp[l*DD];
            float xv  = xp[l*DD];
            float dtx = dtv * xv;
            float y = 0.f;
            #pragma unroll
            for (int n=0;n<NS;n++) {
                float dA = __expf(dtv * an[n]);
                h[n] = fmaf(dA, h[n], dtx*Bsh[l*NS+n]);
                y = fmaf(h[n], Csh[l*NS+n], y);
            }
            yp[l*DD] = fmaf(xv, Dp, y);
        }
    }
}

// ---------------- launch ----------------
extern "C" void kernel_launch(void* const* d_in, const int* in_sizes, int n_in,
                              void* d_out, int out_size) {
    const float* x     = (const float*)d_in[0];
    const float* Wx    = (const float*)d_in[1];
    const float* Wdt   = (const float*)d_in[2];
    const float* bdt   = (const float*)d_in[3];
    const float* A_log = (const float*)d_in[4];
    const float* Dp    = (const float*)d_in[5];
    float* out = (float*)d_out;

    gemm1_partial<<<dim3(BB*LL/G1_BM, 8), 96>>>(x, Wx);
    gemm1_reduce<<<BB*LL*EE/4/256, 256>>>();
    gemm2_softplus<<<dim3(BB*LL/64, DD/128), 128>>>(Wdt, bdt, x, A_log);

    scan_pass1<<<dim3(DD/128, BB, NC), 128>>>(x, A_log);
    scan_pass2<<<BB*DD*NS/256, 256>>>();
    scan_pass3<<<dim3(DD/128, BB, NC), 128>>>(x, A_log, Dp, out);
}

// round 5
// speedup vs baseline: 1.5543x; 1.5543x over previous
#include <cuda_runtime.h>

#define BB 2
#define LL 2048
#define DD 1024
#define NS 16
#define RR 64
#define EE 96
#define NC 32
#define LC 64   /* LL / NC */
#define ST 32   /* sub-tile steps staged in smem */

typedef unsigned long long u64;

// ---------------- packed f32x2 helpers ----------------
__device__ __forceinline__ u64 pk2(float x, float y) {
    u64 r; asm("mov.b64 %0,{%1,%2};" : "=l"(r) : "f"(x), "f"(y)); return r;
}
__device__ __forceinline__ float2 upk(u64 v) {
    float2 f; asm("mov.b64 {%0,%1},%2;" : "=f"(f.x), "=f"(f.y) : "l"(v)); return f;
}
__device__ __forceinline__ u64 fma2_(u64 a, u64 b, u64 c) {
    u64 d; asm("fma.rn.f32x2 %0,%1,%2,%3;" : "=l"(d) : "l"(a), "l"(b), "l"(c)); return d;
}
__device__ __forceinline__ u64 mul2_(u64 a, u64 b) {
    u64 d; asm("mul.rn.f32x2 %0,%1,%2;" : "=l"(d) : "l"(a), "l"(b)); return d;
}

// ---------------- scratch ----------------
__device__ float g_part[8 * BB*LL * EE];     // GEMM1 split-K partials
__device__ float g_xdbl[BB*LL*EE];           // (b,l,96): [0:64)=dt_in, [64:80)=B, [80:96)=C
__device__ float g_dt[BB*LL*DD];             // softplus(dt_proj)
__device__ u64   g_P  [NC*BB*DD*8];          // per-chunk cumulative dA product (packed pairs)
__device__ u64   g_S  [NC*BB*DD*8];          // per-chunk local final state
__device__ u64   g_hin[NC*BB*DD*8];          // corrected chunk-entry state

// =========================================================================
// GEMM1 (split-K partials)
// =========================================================================
#define G1_BM 64
#define G1_BN 96
#define G1_BK 32
#define G1_KC 128

__global__ void __launch_bounds__(96) gemm1_partial(
    const float* __restrict__ X, const float* __restrict__ Wx)
{
    __shared__ float As[G1_BK][G1_BM + 4];
    __shared__ float Bs[G1_BK][G1_BN + 4];
    const int t  = threadIdx.x;
    const int tx = t % 12;
    const int ty = t / 12;
    const int m0 = blockIdx.x * G1_BM;
    const int ks = blockIdx.y;

    u64 acc[8][4];
    #pragma unroll
    for (int i = 0; i < 8; i++)
        #pragma unroll
        for (int j = 0; j < 4; j++) acc[i][j] = 0ull;

    for (int kt = 0; kt < G1_KC / G1_BK; kt++) {
        const int k0 = ks * G1_KC + kt * G1_BK;
        for (int i = t; i < 512; i += 96) {
            int row = i >> 3, q = i & 7;
            float4 v = *(const float4*)&X[(m0 + row) * DD + k0 + q * 4];
            As[q*4+0][row] = v.x; As[q*4+1][row] = v.y;
            As[q*4+2][row] = v.z; As[q*4+3][row] = v.w;
        }
        for (int i = t; i < 768; i += 96) {
            int n = i >> 3, q = i & 7;
            float4 v = *(const float4*)&Wx[n * DD + k0 + q * 4];
            Bs[q*4+0][n] = v.x; Bs[q*4+1][n] = v.y;
            Bs[q*4+2][n] = v.z; Bs[q*4+3][n] = v.w;
        }
        __syncthreads();
        #pragma unroll
        for (int kk = 0; kk < G1_BK; kk++) {
            float4 av0 = *(const float4*)&As[kk][ty * 8];
            float4 av1 = *(const float4*)&As[kk][ty * 8 + 4];
            ulonglong2 bq0 = *(const ulonglong2*)&Bs[kk][tx * 8];
            ulonglong2 bq1 = *(const ulonglong2*)&Bs[kk][tx * 8 + 4];
            u64 b2[4] = {bq0.x, bq0.y, bq1.x, bq1.y};
            float a[8] = {av0.x, av0.y, av0.z, av0.w, av1.x, av1.y, av1.z, av1.w};
            #pragma unroll
            for (int i = 0; i < 8; i++) {
                u64 a2 = pk2(a[i], a[i]);
                #pragma unroll
                for (int j = 0; j < 4; j++)
                    acc[i][j] = fma2_(a2, b2[j], acc[i][j]);
            }
        }
        __syncthreads();
    }

    float* outp = g_part + (size_t)ks * (BB*LL*EE);
    #pragma unroll
    for (int i = 0; i < 8; i++) {
        int m = m0 + ty * 8 + i;
        float2 p0 = upk(acc[i][0]), p1 = upk(acc[i][1]);
        float2 p2 = upk(acc[i][2]), p3 = upk(acc[i][3]);
        *(float4*)&outp[m * EE + tx * 8]     = make_float4(p0.x, p0.y, p1.x, p1.y);
        *(float4*)&outp[m * EE + tx * 8 + 4] = make_float4(p2.x, p2.y, p3.x, p3.y);
    }
}

__global__ void __launch_bounds__(256) gemm1_reduce()
{
    const int i = blockIdx.x * 256 + threadIdx.x;      // < 98304
    const float4* p = (const float4*)g_part;
    float4 s = p[i];
    #pragma unroll
    for (int ks = 1; ks < 8; ks++) {
        float4 v = p[ks * 98304 + i];
        s.x += v.x; s.y += v.y; s.z += v.z; s.w += v.w;
    }
    ((float4*)g_xdbl)[i] = s;
}

// =========================================================================
// GEMM2 + softplus
// =========================================================================
__global__ void __launch_bounds__(128) gemm2_softplus(
    const float* __restrict__ Wdt, const float* __restrict__ bdt)
{
    __shared__ float As[32][64 + 4];
    __shared__ float Bs[32][128 + 4];
    const int t  = threadIdx.x;
    const int tx = t % 16;
    const int ty = t / 16;
    const int m0 = blockIdx.x * 64;
    const int n0 = blockIdx.y * 128;

    u64 acc[8][4];
    #pragma unroll
    for (int i = 0; i < 8; i++)
        #pragma unroll
        for (int j = 0; j < 4; j++) acc[i][j] = 0ull;

    for (int kt = 0; kt < 2; kt++) {
        const int k0 = kt * 32;
        for (int i = t; i < 512; i += 128) {
            int row = i >> 3, q = i & 7;
            float4 v = *(const float4*)&g_xdbl[(m0 + row) * EE + k0 + q * 4];
            As[q*4+0][row] = v.x; As[q*4+1][row] = v.y;
            As[q*4+2][row] = v.z; As[q*4+3][row] = v.w;
        }
        for (int i = t; i < 1024; i += 128) {
            int n = i >> 3, q = i & 7;
            float4 v = *(const float4*)&Wdt[(n0 + n) * RR + k0 + q * 4];
            Bs[q*4+0][n] = v.x; Bs[q*4+1][n] = v.y;
            Bs[q*4+2][n] = v.z; Bs[q*4+3][n] = v.w;
        }
        __syncthreads();
        #pragma unroll
        for (int kk = 0; kk < 32; kk++) {
            float4 av0 = *(const float4*)&As[kk][ty * 8];
            float4 av1 = *(const float4*)&As[kk][ty * 8 + 4];
            ulonglong2 bq0 = *(const ulonglong2*)&Bs[kk][tx * 8];
            ulonglong2 bq1 = *(const ulonglong2*)&Bs[kk][tx * 8 + 4];
            u64 b2[4] = {bq0.x, bq0.y, bq1.x, bq1.y};
            float a[8] = {av0.x, av0.y, av0.z, av0.w, av1.x, av1.y, av1.z, av1.w};
            #pragma unroll
            for (int i = 0; i < 8; i++) {
                u64 a2 = pk2(a[i], a[i]);
                #pragma unroll
                for (int j = 0; j < 4; j++)
                    acc[i][j] = fma2_(a2, b2[j], acc[i][j]);
            }
        }
        __syncthreads();
    }

    float4 bi0 = *(const float4*)&bdt[n0 + tx * 8];
    float4 bi1 = *(const float4*)&bdt[n0 + tx * 8 + 4];
    float bi[8] = {bi0.x, bi0.y, bi0.z, bi0.w, bi1.x, bi1.y, bi1.z, bi1.w};
    #pragma unroll
    for (int i = 0; i < 8; i++) {
        int m = m0 + ty * 8 + i;
        float2 p[4] = {upk(acc[i][0]), upk(acc[i][1]), upk(acc[i][2]), upk(acc[i][3])};
        float v[8] = {p[0].x, p[0].y, p[1].x, p[1].y, p[2].x, p[2].y, p[3].x, p[3].y};
        #pragma unroll
        for (int j = 0; j < 8; j++) {
            float w = v[j] + bi[j];
            v[j] = (w > 20.f) ? w : log1pf(__expf(w));
        }
        *(float4*)&g_dt[m * DD + n0 + tx * 8]     = make_float4(v[0], v[1], v[2], v[3]);
        *(float4*)&g_dt[m * DD + n0 + tx * 8 + 4] = make_float4(v[4], v[5], v[6], v[7]);
    }
}

// ---------------- packed power ladder: dA2[k] = (e1^(2k+1), e1^(2k+2)) ----------------
__device__ __forceinline__ void pow_ladder2(float e1, u64* dA2) {
    float e2 = e1*e1, e4 = e2*e2, e8 = e4*e4;
    u64 d01 = pk2(e1, e2);
    u64 s2 = pk2(e2, e2), s4 = pk2(e4, e4), s8 = pk2(e8, e8);
    dA2[0] = d01;
    dA2[1] = mul2_(d01, s2);
    dA2[2] = mul2_(d01, s4);
    dA2[3] = mul2_(dA2[1], s4);
    dA2[4] = mul2_(d01, s8);
    dA2[5] = mul2_(dA2[1], s8);
    dA2[6] = mul2_(dA2[2], s8);
    dA2[7] = mul2_(dA2[3], s8);
}

// ---------------- pass 1: per-chunk local scan, emit (P, S) ----------------
__global__ void __launch_bounds__(128) scan_pass1(
    const float* __restrict__ x, const float* __restrict__ A_log)
{
    __shared__ alignas(16) float Bsh[LC*NS];        // 4KB
    __shared__ alignas(16) float dts[ST][128];      // 16KB
    __shared__ alignas(16) float xs [ST][128];      // 16KB
    const int tid = threadIdx.x;
    const int d0 = blockIdx.x*128;
    const int d = d0 + tid;
    const int b = blockIdx.y;
    const int c = blockIdx.z;
    const int l0 = c*LC;

    for (int i = tid; i < LC*NS; i += 128) {
        int l = i >> 4, n = i & 15;
        Bsh[i] = g_xdbl[(b*LL + l0 + l)*EE + RR + n];
    }

    float an[NS];
    #pragma unroll
    for (int n=0;n<NS;n++) an[n] = -__expf(A_log[d*NS+n]);
    const float a0 = an[0];
    bool chain = true;
    #pragma unroll
    for (int n=1;n<NS;n++)
        chain = chain && (fabsf(an[n] - (float)(n+1)*a0) <= 2e-5f*(float)(n+1));

    const float* dtg = g_dt + (size_t)(b*LL + l0)*DD + d0;
    const float* xg  = x    + (size_t)(b*LL + l0)*DD + d0;
    const int base8 = ((c*BB + b)*DD + d)*8;

    u64 h2[8];
    #pragma unroll
    for (int k=0;k<8;k++) h2[k] = 0ull;
    float hg[NS], Pg[NS];
    #pragma unroll
    for (int n=0;n<NS;n++) { hg[n]=0.f; Pg[n]=1.f; }
    float E = 1.f;

    for (int s = 0; s < LC/ST; s++) {
        __syncthreads();
        #pragma unroll
        for (int i = 0; i < ST*32/128; i++) {         // 8 float4 per thread per array
            int lin = tid + i*128;
            int r = lin >> 5, cc = lin & 31;
            *(float4*)&dts[r][cc*4] = *(const float4*)&dtg[(s*ST + r)*DD + cc*4];
            *(float4*)&xs [r][cc*4] = *(const float4*)&xg [(s*ST + r)*DD + cc*4];
        }
        __syncthreads();

        if (chain) {
            #pragma unroll 4
            for (int l = 0; l < ST; l++) {
                float dtv = dts[l][tid];
                float xv  = xs[l][tid];
                float dtx = dtv * xv;
                u64 dtx2 = pk2(dtx, dtx);
                float e1 = __expf(dtv * a0);
                E *= e1;
                u64 dA2[8];
                pow_ladder2(e1, dA2);
                const u64* Bp = (const u64*)(Bsh + (s*ST + l)*NS);
                #pragma unroll
                for (int k=0;k<8;k++)
                    h2[k] = fma2_(dA2[k], h2[k], mul2_(dtx2, Bp[k]));
            }
        } else {
            for (int l = 0; l < ST; l++) {
                float dtv = dts[l][tid];
                float dtx = dtv * xs[l][tid];
                #pragma unroll
                for (int n=0;n<NS;n++) {
                    float dA = __expf(dtv * an[n]);
                    Pg[n] *= dA;
                    hg[n] = fmaf(dA, hg[n], dtx*Bsh[(s*ST+l)*NS+n]);
                }
            }
        }
    }

    if (chain) {
        u64 P2[8];
        pow_ladder2(E, P2);
        #pragma unroll
        for (int k=0;k<8;k++) { g_P[base8+k] = P2[k]; g_S[base8+k] = h2[k]; }
    } else {
        #pragma unroll
        for (int k=0;k<8;k++) { g_P[base8+k] = pk2(Pg[2*k],Pg[2*k+1]); g_S[base8+k] = pk2(hg[2*k],hg[2*k+1]); }
    }
}

// ---------------- pass 2: sequential chunk combine ----------------
__global__ void __launch_bounds__(256) scan_pass2()
{
    const int i = blockIdx.x*256 + threadIdx.x;     // over BB*DD*NS = 32768
    const float* Pf = (const float*)g_P;
    const float* Sf = (const float*)g_S;
    float* Hf = (float*)g_hin;
    float h = 0.f;
    #pragma unroll
    for (int c = 0; c < NC; c++) {
        int idx = c*(BB*DD*NS) + i;
        Hf[idx] = h;
        h = fmaf(Pf[idx], h, Sf[idx]);
    }
}

// ---------------- pass 3: final scan with corrected h0, emit y ----------------
__global__ void __launch_bounds__(128) scan_pass3(
    const float* __restrict__ x, const float* __restrict__ A_log,
    const float* __restrict__ Dparam, float* __restrict__ out)
{
    __shared__ alignas(16) float Bsh[LC*NS];        // 4KB
    __shared__ alignas(16) float Csh[LC*NS];        // 4KB
    __shared__ alignas(16) float dts[ST][128];      // 16KB
    __shared__ alignas(16) float xs [ST][128];      // 16KB
    const int tid = threadIdx.x;
    const int d0 = blockIdx.x*128;
    const int d = d0 + tid;
    const int b = blockIdx.y;
    const int c = blockIdx.z;
    const int l0 = c*LC;

    for (int i = tid; i < LC*NS; i += 128) {
        int l = i >> 4, n = i & 15;
        int base = (b*LL + l0 + l)*EE + RR;
        Bsh[i] = g_xdbl[base + n];
        Csh[i] = g_xdbl[base + NS + n];
    }

    float an[NS];
    #pragma unroll
    for (int n=0;n<NS;n++) an[n] = -__expf(A_log[d*NS+n]);
    const float a0 = an[0];
    bool chain = true;
    #pragma unroll
    for (int n=1;n<NS;n++)
        chain = chain && (fabsf(an[n] - (float)(n+1)*a0) <= 2e-5f*(float)(n+1));

    const int base8 = ((c*BB + b)*DD + d)*8;
    const float Dp = Dparam[d];
    const float* dtg = g_dt + (size_t)(b*LL + l0)*DD + d0;
    const float* xg  = x    + (size_t)(b*LL + l0)*DD + d0;
    float* yp        = out  + (size_t)(b*LL + l0)*DD + d;

    u64 h2[8];
    #pragma unroll
    for (int k=0;k<8;k++) h2[k] = g_hin[base8+k];
    float hg[NS];
    #pragma unroll
    for (int k=0;k<8;k++) { float2 v = upk(h2[k]); hg[2*k]=v.x; hg[2*k+1]=v.y; }

    for (int s = 0; s < LC/ST; s++) {
        __syncthreads();
        #pragma unroll
        for (int i = 0; i < ST*32/128; i++) {
            int lin = tid + i*128;
            int r = lin >> 5, cc = lin & 31;
            *(float4*)&dts[r][cc*4] = *(const float4*)&dtg[(s*ST + r)*DD + cc*4];
            *(float4*)&xs [r][cc*4] = *(const float4*)&xg [(s*ST + r)*DD + cc*4];
        }
        __syncthreads();

        if (chain) {
            #pragma unroll 4
            for (int l = 0; l < ST; l++) {
                float dtv = dts[l][tid];
                float xv  = xs[l][tid];
                float dtx = dtv * xv;
                u64 dtx2 = pk2(dtx, dtx);
                float e1 = __expf(dtv * a0);
                u64 dA2[8];
                pow_ladder2(e1, dA2);
                const u64* Bp = (const u64*)(Bsh + (s*ST + l)*NS);
                const u64* Cp = (const u64*)(Csh + (s*ST + l)*NS);
                u64 y2a = 0ull, y2b = 0ull;
                #pragma unroll
                for (int k=0;k<8;k+=2) {
                    h2[k]   = fma2_(dA2[k],   h2[k],   mul2_(dtx2, Bp[k]));
                    h2[k+1] = fma2_(dA2[k+1], h2[k+1], mul2_(dtx2, Bp[k+1]));
                    y2a = fma2_(h2[k],   Cp[k],   y2a);
                    y2b = fma2_(h2[k+1], Cp[k+1], y2b);
                }
                float2 ya = upk(y2a), yb = upk(y2b);
                yp[(s*ST + l)*DD] = fmaf(xv, Dp, (ya.x+ya.y)+(yb.x+yb.y));
            }
        } else {
            for (int l = 0; l < ST; l++) {
                float dtv = dts[l][tid];
                float xv  = xs[l][tid];
                float dtx = dtv * xv;
                float y = 0.f;
                #pragma unroll
                for (int n=0;n<NS;n++) {
                    float dA = __expf(dtv * an[n]);
                    hg[n] = fmaf(dA, hg[n], dtx*Bsh[(s*ST+l)*NS+n]);
                    y = fmaf(hg[n], Csh[(s*ST+l)*NS+n], y);
                }
                yp[(s*ST + l)*DD] = fmaf(xv, Dp, y);
            }
        }
    }
}

// ---------------- launch ----------------
extern "C" void kernel_launch(void* const* d_in, const int* in_sizes, int n_in,
                              void* d_out, int out_size) {
    const float* x     = (const float*)d_in[0];
    const float* Wx    = (const float*)d_in[1];
    const float* Wdt   = (const float*)d_in[2];
    const float* bdt   = (const float*)d_in[3];
    const float* A_log = (const float*)d_in[4];
    const float* Dp    = (const float*)d_in[5];
    float* out = (float*)d_out;

    gemm1_partial<<<dim3(BB*LL/G1_BM, 8), 96>>>(x, Wx);
    gemm1_reduce<<<BB*LL*EE/4/256, 256>>>();
    gemm2_softplus<<<dim3(BB*LL/64, DD/128), 128>>>(Wdt, bdt);

    scan_pass1<<<dim3(DD/128, BB, NC), 128>>>(x, A_log);
    scan_pass2<<<BB*DD*NS/256, 256>>>();
    scan_pass3<<<dim3(DD/128, BB, NC), 128>>>(x, A_log, Dp, out);
}